// round 15
// baseline (speedup 1.0000x reference)
#include <cuda_runtime.h>
#include <cuda_fp16.h>
#include <cstdint>

// ---------------------------------------------------------------- constants
#define T_DIM 1024
#define D_DIM 4096
#define O_DIM 4096
#define R_DIM 16
#define L_DIM 16
#define NEXT  256
#define BROWS (O_DIM + NEXT)            // 4352

#define BM 128
#define BN 128
#define BK 32                           // halves per ktile
#define KT (D_DIM / BK)                 // 128
#define NT_W (O_DIM / BN)               // 32
#define NTILES (NT_W + NEXT / BN)       // 34 -> grid 34 x 8 = 272 blocks

#define SROW 20                         // smem row stride in words (16 data + 4 pad)
#define TILE_W (BM * SROW)              // 2560 words per operand tile
#define STG_W (2 * TILE_W)              // A+B per stage = 20480 B
#define NSTAGE 3
#define SMEM_BYTES (NSTAGE * STG_W * 4) // 61440 B -> 2 CTAs/SM

#define ESEG 4                          // expand: token-list split factor

// convert-pass sizes (float4 units)
#define W4   (O_DIM * D_DIM / 4)
#define LA4  (NEXT * D_DIM / 4)
#define X4   (T_DIM * D_DIM / 4)
#define TOT4 (W4 + LA4 + X4)

// ---------------------------------------------------------------- scratch
__device__ __align__(16) __half g_ah[T_DIM * D_DIM];    // X in fp16
__device__ __align__(16) __half g_bh[BROWS * D_DIM];    // [W ; lora_a] in fp16
__device__ __align__(16) float g_act[T_DIM * NEXT];

__device__ __forceinline__ void mma_f16(float* c, const uint32_t* a, const uint32_t* b) {
    asm volatile(
        "mma.sync.aligned.m16n8k16.row.col.f32.f16.f16.f32 "
        "{%0,%1,%2,%3}, {%4,%5,%6,%7}, {%8,%9}, {%0,%1,%2,%3};"
        : "+f"(c[0]), "+f"(c[1]), "+f"(c[2]), "+f"(c[3])
        : "r"(a[0]), "r"(a[1]), "r"(a[2]), "r"(a[3]), "r"(b[0]), "r"(b[1]));
}
__device__ __forceinline__ void ldsm4(uint32_t* r, uint32_t addr) {
    asm volatile("ldmatrix.sync.aligned.m8n8.x4.shared.b16 {%0,%1,%2,%3}, [%4];"
                 : "=r"(r[0]), "=r"(r[1]), "=r"(r[2]), "=r"(r[3]) : "r"(addr));
}
__device__ __forceinline__ void cp16(uint32_t dst, const void* src) {
    asm volatile("cp.async.cg.shared.global [%0], [%1], 16;" :: "r"(dst), "l"(src));
}

// ---------------------------------------------------------------- K0: fp32 -> fp16 convert
__global__ void __launch_bounds__(256) convert_kernel(
    const float4* __restrict__ w4, const float4* __restrict__ la4,
    const float4* __restrict__ x4) {
    const size_t idx = (size_t)blockIdx.x * 256 + threadIdx.x;
    if (idx >= TOT4) return;
    float4 v;
    uint2* dst;
    if (idx < W4 + LA4) {
        v = (idx < W4) ? w4[idx] : la4[idx - W4];
        dst = reinterpret_cast<uint2*>(g_bh) + idx;
    } else {
        v = x4[idx - W4 - LA4];
        dst = reinterpret_cast<uint2*>(g_ah) + (idx - W4 - LA4);
    }
    half2 h0 = __floats2half2_rn(v.x, v.y);
    half2 h1 = __floats2half2_rn(v.z, v.w);
    uint2 u;
    u.x = *reinterpret_cast<uint32_t*>(&h0);
    u.y = *reinterpret_cast<uint32_t*>(&h1);
    *dst = u;
}

// ---------------------------------------------------------------- K1: fp16 GEMM — R8 shape + cp.async + frag double-buffer
// grid (34, 8). bx<32 -> out (+bias); bx>=32 -> g_act. 8 warps 2m x 4n, warp 64x32, 2 CTAs/SM.
__global__ __launch_bounds__(256, 2) void gemm_kernel(
    const float* __restrict__ bias, float* __restrict__ out) {
    extern __shared__ uint32_t smem[];
    const uint32_t sb = (uint32_t)__cvta_generic_to_shared(smem);

    const int tid = threadIdx.x;
    const int bx = blockIdx.x, by = blockIdx.y;
    const int warp = tid >> 5, lane = tid & 31;
    const int wm = warp & 1;
    const int wn = warp >> 1;
    const int gid = lane >> 2;
    const int tig = lane & 3;

    // ldmatrix per-lane base offsets (words) — R8-proven mapping
    const int aOff0 = (wm * 64 + (lane & 15)) * SROW + (lane >> 4) * 4;
    const int bOff0 = (wn * 32 + ((lane >> 4) & 1) * 8 + (lane & 7)) * SROW
                    + ((lane >> 3) & 1) * 4;

    // cp.async mapping (R7-proven): row = tid>>1, 32B half-row
    const int ar = tid >> 1;
    const int ac = (tid & 1) * 2;
    const __half* aA = g_ah + (size_t)(by * BM + ar) * D_DIM + ac * 8;
    const __half* aB = g_bh + (size_t)(bx * BN + ar) * D_DIM + ac * 8;
    const uint32_t dA = sb + (ar * SROW + ac * 4) * 4;
    const uint32_t dB = dA + TILE_W * 4;

#define ISSUE(st, kt) do {                                                    \
    const uint32_t so = (uint32_t)(st) * STG_W * 4;                           \
    const int ko = (kt) * BK;                                                 \
    cp16(dA + so,      aA + ko);                                              \
    cp16(dA + so + 16, aA + ko + 8);                                          \
    cp16(dB + so,      aB + ko);                                              \
    cp16(dB + so + 16, aB + ko + 8);                                          \
    asm volatile("cp.async.commit_group;" ::: "memory");                      \
} while (0)

#define LOADFRAGS(dstbuf, kkv) do {                                           \
    const int kb4 = (kkv) * 32;                                               \
    _Pragma("unroll")                                                         \
    for (int mi = 0; mi < 4; mi++)                                            \
        ldsm4(af[dstbuf][mi], aBase + mi * 16 * SROW * 4 + kb4);              \
    _Pragma("unroll")                                                         \
    for (int nj = 0; nj < 2; nj++) {                                          \
        uint32_t br[4];                                                       \
        ldsm4(br, bBase + nj * 16 * SROW * 4 + kb4);                          \
        bf[dstbuf][nj * 2 + 0][0] = br[0]; bf[dstbuf][nj * 2 + 0][1] = br[1]; \
        bf[dstbuf][nj * 2 + 1][0] = br[2]; bf[dstbuf][nj * 2 + 1][1] = br[3]; \
    }                                                                         \
} while (0)

    float acc[4][4][4];
#pragma unroll
    for (int mi = 0; mi < 4; mi++)
#pragma unroll
        for (int ni = 0; ni < 4; ni++)
#pragma unroll
            for (int c = 0; c < 4; c++) acc[mi][ni][c] = 0.0f;

    ISSUE(0, 0);
    ISSUE(1, 1);

    uint32_t af[2][4][4], bf[2][4][2];
    int st = 0;
    for (int kt = 0; kt < KT; kt++) {
        if (kt == KT - 1)
            asm volatile("cp.async.wait_group 0;" ::: "memory");
        else
            asm volatile("cp.async.wait_group 1;" ::: "memory");
        __syncthreads();

        const uint32_t aBase = sb + 4 * (st * STG_W + aOff0);
        const uint32_t bBase = sb + 4 * (st * STG_W + TILE_W + bOff0);

        LOADFRAGS(0, 0);                       // kk=0 frags
        if (kt + 2 < KT) {
            const int ns = (st + 2 >= NSTAGE) ? st + 2 - NSTAGE : st + 2;
            ISSUE(ns, kt + 2);
        }
        LOADFRAGS(1, 1);                       // kk=1 frags (overlap with kk=0 MMAs)
#pragma unroll
        for (int mi = 0; mi < 4; mi++)
#pragma unroll
            for (int ni = 0; ni < 4; ni++)
                mma_f16(acc[mi][ni], af[0][mi], bf[0][ni]);
#pragma unroll
        for (int mi = 0; mi < 4; mi++)
#pragma unroll
            for (int ni = 0; ni < 4; ni++)
                mma_f16(acc[mi][ni], af[1][mi], bf[1][ni]);

        st = (st + 1 == NSTAGE) ? 0 : st + 1;
    }

    // epilogue
#pragma unroll
    for (int mi = 0; mi < 4; mi++) {
        const int row0 = by * BM + wm * 64 + mi * 16 + gid;
        if (bx < NT_W) {
#pragma unroll
            for (int ni = 0; ni < 4; ni++) {
                const int col0 = bx * BN + wn * 32 + ni * 8 + tig * 2;
                const float b0 = bias[col0], b1 = bias[col0 + 1];
                float2 v0 = make_float2(acc[mi][ni][0] + b0, acc[mi][ni][1] + b1);
                float2 v1 = make_float2(acc[mi][ni][2] + b0, acc[mi][ni][3] + b1);
                *reinterpret_cast<float2*>(&out[(size_t)row0 * O_DIM + col0]) = v0;
                *reinterpret_cast<float2*>(&out[(size_t)(row0 + 8) * O_DIM + col0]) = v1;
            }
        } else {
#pragma unroll
            for (int ni = 0; ni < 4; ni++) {
                const int col0 = (bx - NT_W) * BN + wn * 32 + ni * 8 + tig * 2;
                float2 v0 = make_float2(acc[mi][ni][0], acc[mi][ni][1]);
                float2 v1 = make_float2(acc[mi][ni][2], acc[mi][ni][3]);
                *reinterpret_cast<float2*>(&g_act[(size_t)row0 * NEXT + col0]) = v0;
                *reinterpret_cast<float2*>(&g_act[(size_t)(row0 + 8) * NEXT + col0]) = v1;
            }
        }
    }
}

// ---------------------------------------------------------------- K2: LoRA expand v3 — staged via shared (16B-aligned!)
// grid (L, O/256, ESEG). idxs staged to shared (parallel) -> fast ballot compaction;
// segment a-vectors staged to shared (parallel) -> streaming independent RMWs.
__global__ void __launch_bounds__(256) lora_expand_kernel(
    const float* __restrict__ lb, const int* __restrict__ idxs,
    float* __restrict__ out) {
    __shared__ __align__(16) int sidx[T_DIM];
    __shared__ int lst[T_DIM];
    __shared__ int scnt;
    __shared__ __align__(16) float sa[256 * R_DIM];   // up to 256 tokens/segment

    const int l = blockIdx.x;
    const int tid = threadIdx.x;
    const int lane = tid & 31;

    // stage idxs (1024 ints) via int4: 256 threads x 1 load
    reinterpret_cast<int4*>(sidx)[tid] = reinterpret_cast<const int4*>(idxs)[tid];
    __syncthreads();

    if (tid < 32) {
        int c = 0;
#pragma unroll 8
        for (int base = 0; base < T_DIM; base += 32) {
            const int v = sidx[base + lane];
            const unsigned m = __ballot_sync(0xffffffffu, v == l);
            if (v == l) lst[c + __popc(m & ((1u << lane) - 1u))] = base + lane;
            c += __popc(m);
        }
        if (lane == 0) scnt = c;
    }
    __syncthreads();
    const int n = scnt;
    const int per = (n + ESEG - 1) / ESEG;
    const int i0 = blockIdx.z * per;
    const int i1 = min(n, i0 + per);
    if (i0 >= i1) return;
    const int m = i1 - i0;

    // stage a-vectors for this segment: m*16 floats, fully parallel
    for (int f = tid; f < m * R_DIM; f += 256) {
        const int t = lst[i0 + (f >> 4)];
        sa[f] = g_act[(size_t)t * NEXT + l * R_DIM + (f & 15)];
    }
    __syncthreads();

    const int o = blockIdx.y * 256 + tid;
    const float4* bp = (const float4*)(lb + ((size_t)l * O_DIM + o) * R_DIM);
    const float4 b0 = bp[0], b1 = bp[1], b2 = bp[2], b3 = bp[3];

#pragma unroll 4
    for (int i = 0; i < m; i++) {
        const float4* a = (const float4*)(sa + i * R_DIM);
        const float4 a0 = a[0], a1 = a[1], a2 = a[2], a3 = a[3];
        float y = a0.x * b0.x + a0.y * b0.y + a0.z * b0.z + a0.w * b0.w
                + a1.x * b1.x + a1.y * b1.y + a1.z * b1.z + a1.w * b1.w
                + a2.x * b2.x + a2.y * b2.y + a2.z * b2.z + a2.w * b2.w
                + a3.x * b3.x + a3.y * b3.y + a3.z * b3.z + a3.w * b3.w;
        out[(size_t)lst[i0 + i] * O_DIM + o] += y;
    }
}

// ---------------------------------------------------------------- launch
extern "C" void kernel_launch(void* const* d_in, const int* in_sizes, int n_in,
                              void* d_out, int out_size) {
    const float* x    = (const float*)d_in[0];   // [T, D]
    const float* w    = (const float*)d_in[1];   // [O, D]
    const float* bias = (const float*)d_in[2];   // [O]
    const float* la   = (const float*)d_in[3];   // [L,1,R,D] -> flat [256, D]
    const float* lb   = (const float*)d_in[4];   // [L,1,O,R]
    const int* idxs   = (const int*)d_in[5];     // [T]
    float* out        = (float*)d_out;           // [T, O]

    cudaFuncSetAttribute(gemm_kernel,
                         cudaFuncAttributeMaxDynamicSharedMemorySize, SMEM_BYTES);

    convert_kernel<<<(TOT4 + 255) / 256, 256>>>(
        (const float4*)w, (const float4*)la, (const float4*)x);
    gemm_kernel<<<dim3(NTILES, T_DIM / BM), 256, SMEM_BYTES>>>(bias, out);
    lora_expand_kernel<<<dim3(L_DIM, O_DIM / 256, ESEG), 256>>>(lb, idxs, out);
}

// round 16
// speedup vs baseline: 1.7793x; 1.7793x over previous
#include <cuda_runtime.h>
#include <cuda_fp16.h>
#include <cstdint>

// ---------------------------------------------------------------- constants
#define T_DIM 1024
#define D_DIM 4096
#define O_DIM 4096
#define R_DIM 16
#define L_DIM 16
#define NEXT  256

#define BM 128
#define BN 128
#define BK 32                           // halves per ktile
#define KT (D_DIM / BK)                 // 128
#define NT_W (O_DIM / BN)               // 32
#define NTILES (NT_W + NEXT / BN)       // 34 -> grid 34 x 8 = 272 blocks
#define SROW 20                         // smem row stride in words (16 data + 4 pad)
#define TILE_W (BM * SROW)              // 2560 words per tile buffer

#define ESEG 4                          // expand: token-list split factor

// ---------------------------------------------------------------- scratch
__device__ __align__(16) float g_act[T_DIM * NEXT];

__device__ __forceinline__ uint32_t pack_h2(float lo, float hi) {
    half2 h = __floats2half2_rn(lo, hi);
    return *reinterpret_cast<uint32_t*>(&h);
}
__device__ __forceinline__ void mma_f16(float* c, const uint32_t* a, const uint32_t* b) {
    asm volatile(
        "mma.sync.aligned.m16n8k16.row.col.f32.f16.f16.f32 "
        "{%0,%1,%2,%3}, {%4,%5,%6,%7}, {%8,%9}, {%0,%1,%2,%3};"
        : "+f"(c[0]), "+f"(c[1]), "+f"(c[2]), "+f"(c[3])
        : "r"(a[0]), "r"(a[1]), "r"(a[2]), "r"(a[3]), "r"(b[0]), "r"(b[1]));
}
__device__ __forceinline__ void ldsm4(uint32_t* r, uint32_t addr) {
    asm volatile("ldmatrix.sync.aligned.m8n8.x4.shared.b16 {%0,%1,%2,%3}, [%4];"
                 : "=r"(r[0]), "=r"(r[1]), "=r"(r[2]), "=r"(r[3]) : "r"(addr));
}

// ---------------------------------------------------------------- K1: fp16 GEMM — R8/R13 proven structure, UNCHANGED
// grid (34, 8). bx<32 -> out (+bias); bx>=32 -> g_act. 8 warps 2m x 4n, warp 64x32, 2 CTAs/SM.
__global__ __launch_bounds__(256, 2) void gemm_kernel(
    const float* __restrict__ X, const float* __restrict__ Wm,
    const float* __restrict__ bias, const float* __restrict__ la,
    float* __restrict__ out) {
    __shared__ uint32_t smem[4 * TILE_W];        // A[2 bufs] then B[2 bufs], 40960 B
    const uint32_t sb = (uint32_t)__cvta_generic_to_shared(smem);

    const int tid = threadIdx.x;
    const int bx = blockIdx.x, by = blockIdx.y;
    const int warp = tid >> 5, lane = tid & 31;
    const int wm = warp & 1;
    const int wn = warp >> 1;
    const int gid = lane >> 2;
    const int tig = lane & 3;

    const int aOff0 = (wm * 64 + (lane & 15)) * SROW + (lane >> 4) * 4;
    const int bOff0 = (wn * 32 + ((lane >> 4) & 1) * 8 + (lane & 7)) * SROW
                    + ((lane >> 3) & 1) * 4;

    const int lr = tid >> 3;
    const int lc = (tid & 7) * 4;
    const int kw = (tid & 7) * 2;

    const float* Asrc = X + (size_t)(by * BM) * D_DIM;
    const float* Bsrc = (bx < NT_W) ? (Wm + (size_t)(bx * BN) * D_DIM)
                                    : (la + (size_t)((bx - NT_W) * BN) * D_DIM);

    float acc[4][4][4];
#pragma unroll
    for (int mi = 0; mi < 4; mi++)
#pragma unroll
        for (int ni = 0; ni < 4; ni++)
#pragma unroll
            for (int c = 0; c < 4; c++) acc[mi][ni][c] = 0.0f;

    float4 regA[4], regB[4];
    uint32_t* As = smem;
    uint32_t* Bs = smem + 2 * TILE_W;

#pragma unroll
    for (int i = 0; i < 4; i++) {
        regA[i] = *reinterpret_cast<const float4*>(Asrc + (size_t)(lr + i * 32) * D_DIM + lc);
        regB[i] = *reinterpret_cast<const float4*>(Bsrc + (size_t)(lr + i * 32) * D_DIM + lc);
    }
#pragma unroll
    for (int i = 0; i < 4; i++) {
        const int ro = (lr + i * 32) * SROW + kw;
        *reinterpret_cast<uint2*>(&As[ro]) =
            make_uint2(pack_h2(regA[i].x, regA[i].y), pack_h2(regA[i].z, regA[i].w));
        *reinterpret_cast<uint2*>(&Bs[ro]) =
            make_uint2(pack_h2(regB[i].x, regB[i].y), pack_h2(regB[i].z, regB[i].w));
    }
    __syncthreads();

    int buf = 0;
    for (int kt = 0; kt < KT; kt++) {
        if (kt < KT - 1) {
            const int kb = (kt + 1) * BK;
#pragma unroll
            for (int i = 0; i < 4; i++) {
                regA[i] = *reinterpret_cast<const float4*>(
                    Asrc + (size_t)(lr + i * 32) * D_DIM + kb + lc);
                regB[i] = *reinterpret_cast<const float4*>(
                    Bsrc + (size_t)(lr + i * 32) * D_DIM + kb + lc);
            }
        }

        const uint32_t aBase = sb + 4 * (buf * TILE_W + aOff0);
        const uint32_t bBase = sb + 4 * ((2 + buf) * TILE_W + bOff0);
#pragma unroll
        for (int kk = 0; kk < 2; kk++) {
            const int kb4 = kk * 32;
            uint32_t af[4][4], bf[4][2];
#pragma unroll
            for (int mi = 0; mi < 4; mi++)
                ldsm4(af[mi], aBase + mi * 16 * SROW * 4 + kb4);
#pragma unroll
            for (int nj = 0; nj < 2; nj++) {
                uint32_t br[4];
                ldsm4(br, bBase + nj * 16 * SROW * 4 + kb4);
                bf[nj * 2 + 0][0] = br[0]; bf[nj * 2 + 0][1] = br[1];
                bf[nj * 2 + 1][0] = br[2]; bf[nj * 2 + 1][1] = br[3];
            }
#pragma unroll
            for (int mi = 0; mi < 4; mi++)
#pragma unroll
                for (int ni = 0; ni < 4; ni++)
                    mma_f16(acc[mi][ni], af[mi], bf[ni]);
        }

        if (kt < KT - 1) {
            const int nbuf = buf ^ 1;
            uint32_t* Aw = As + nbuf * TILE_W;
            uint32_t* Bw = Bs + nbuf * TILE_W;
#pragma unroll
            for (int i = 0; i < 4; i++) {
                const int ro = (lr + i * 32) * SROW + kw;
                *reinterpret_cast<uint2*>(&Aw[ro]) =
                    make_uint2(pack_h2(regA[i].x, regA[i].y), pack_h2(regA[i].z, regA[i].w));
                *reinterpret_cast<uint2*>(&Bw[ro]) =
                    make_uint2(pack_h2(regB[i].x, regB[i].y), pack_h2(regB[i].z, regB[i].w));
            }
            __syncthreads();
            buf = nbuf;
        }
    }

#pragma unroll
    for (int mi = 0; mi < 4; mi++) {
        const int row0 = by * BM + wm * 64 + mi * 16 + gid;
        if (bx < NT_W) {
#pragma unroll
            for (int ni = 0; ni < 4; ni++) {
                const int col0 = bx * BN + wn * 32 + ni * 8 + tig * 2;
                const float b0 = bias[col0], b1 = bias[col0 + 1];
                float2 v0 = make_float2(acc[mi][ni][0] + b0, acc[mi][ni][1] + b1);
                float2 v1 = make_float2(acc[mi][ni][2] + b0, acc[mi][ni][3] + b1);
                *reinterpret_cast<float2*>(&out[(size_t)row0 * O_DIM + col0]) = v0;
                *reinterpret_cast<float2*>(&out[(size_t)(row0 + 8) * O_DIM + col0]) = v1;
            }
        } else {
#pragma unroll
            for (int ni = 0; ni < 4; ni++) {
                const int col0 = (bx - NT_W) * BN + wn * 32 + ni * 8 + tig * 2;
                float2 v0 = make_float2(acc[mi][ni][0], acc[mi][ni][1]);
                float2 v1 = make_float2(acc[mi][ni][2], acc[mi][ni][3]);
                *reinterpret_cast<float2*>(&g_act[(size_t)row0 * NEXT + col0]) = v0;
                *reinterpret_cast<float2*>(&g_act[(size_t)(row0 + 8) * NEXT + col0]) = v1;
            }
        }
    }
}

// ---------------------------------------------------------------- K2: LoRA expand v3 — staged via shared (16B-aligned)
// grid (L, O/256, ESEG). idxs staged to shared (parallel) -> fast ballot compaction;
// segment a-vectors staged to shared (parallel) -> streaming independent RMWs.
__global__ void __launch_bounds__(256) lora_expand_kernel(
    const float* __restrict__ lb, const int* __restrict__ idxs,
    float* __restrict__ out) {
    __shared__ __align__(16) int sidx[T_DIM];
    __shared__ int lst[T_DIM];
    __shared__ int scnt;
    __shared__ __align__(16) float sa[256 * R_DIM];   // up to 256 tokens/segment

    const int l = blockIdx.x;
    const int tid = threadIdx.x;
    const int lane = tid & 31;

    // stage idxs (1024 ints) via int4: 256 threads x 1 load
    reinterpret_cast<int4*>(sidx)[tid] = reinterpret_cast<const int4*>(idxs)[tid];
    __syncthreads();

    if (tid < 32) {
        int c = 0;
#pragma unroll 8
        for (int base = 0; base < T_DIM; base += 32) {
            const int v = sidx[base + lane];
            const unsigned m = __ballot_sync(0xffffffffu, v == l);
            if (v == l) lst[c + __popc(m & ((1u << lane) - 1u))] = base + lane;
            c += __popc(m);
        }
        if (lane == 0) scnt = c;
    }
    __syncthreads();
    const int n = scnt;
    const int per = (n + ESEG - 1) / ESEG;
    const int i0 = blockIdx.z * per;
    const int i1 = min(n, i0 + per);
    if (i0 >= i1) return;
    const int m = i1 - i0;

    // stage a-vectors for this segment: m*16 floats, fully parallel
    for (int f = tid; f < m * R_DIM; f += 256) {
        const int t = lst[i0 + (f >> 4)];
        sa[f] = g_act[(size_t)t * NEXT + l * R_DIM + (f & 15)];
    }
    __syncthreads();

    const int o = blockIdx.y * 256 + tid;
    const float4* bp = (const float4*)(lb + ((size_t)l * O_DIM + o) * R_DIM);
    const float4 b0 = bp[0], b1 = bp[1], b2 = bp[2], b3 = bp[3];

#pragma unroll 4
    for (int i = 0; i < m; i++) {
        const float4* a = (const float4*)(sa + i * R_DIM);
        const float4 a0 = a[0], a1 = a[1], a2 = a[2], a3 = a[3];
        float y = a0.x * b0.x + a0.y * b0.y + a0.z * b0.z + a0.w * b0.w
                + a1.x * b1.x + a1.y * b1.y + a1.z * b1.z + a1.w * b1.w
                + a2.x * b2.x + a2.y * b2.y + a2.z * b2.z + a2.w * b2.w
                + a3.x * b3.x + a3.y * b3.y + a3.z * b3.z + a3.w * b3.w;
        out[(size_t)lst[i0 + i] * O_DIM + o] += y;
    }
}

// ---------------------------------------------------------------- launch
extern "C" void kernel_launch(void* const* d_in, const int* in_sizes, int n_in,
                              void* d_out, int out_size) {
    const float* x    = (const float*)d_in[0];   // [T, D]
    const float* w    = (const float*)d_in[1];   // [O, D]
    const float* bias = (const float*)d_in[2];   // [O]
    const float* la   = (const float*)d_in[3];   // [L,1,R,D] -> flat [256, D]
    const float* lb   = (const float*)d_in[4];   // [L,1,O,R]
    const int* idxs   = (const int*)d_in[5];     // [T]
    float* out        = (float*)d_out;           // [T, O]

    gemm_kernel<<<dim3(NTILES, T_DIM / BM), 256>>>(x, w, bias, la, out);
    lora_expand_kernel<<<dim3(L_DIM, O_DIM / 256, ESEG), 256>>>(lb, idxs, out);
}